// round 1
// baseline (speedup 1.0000x reference)
#include <cuda_runtime.h>
#include <math.h>

#define BB 2
#define NN 8192
#define DD 64
#define KNBR 16
#define NPTS (BB*NN)          // 16384
#define ROWS (NPTS*KNBR)      // 262144

// ---------------- scratch (static device arrays; no allocation) ----------------
__device__ float g_q  [NPTS*DD];
__device__ float g_kf [NPTS*DD];
__device__ float g_vf [NPTS*DD];
__device__ int   g_knn[ROWS];
__device__ float g_res[NPTS*DD];
__device__ float g_sum[DD];
__device__ float g_sumsq[DD];

// ---------------- K1: projections q,k,v = feats @ W (+ zero BN accumulators) ----
// grid 128 blocks x 256 thr; each block: 128 rows. Shared: feats tile transposed + one W.
#define PROJ_SMEM ((64*132 + 64*64)*4)
__global__ void __launch_bounds__(256) proj_kernel(
    const float* __restrict__ feats,
    const float* __restrict__ wq, const float* __restrict__ wk, const float* __restrict__ wv)
{
    extern __shared__ float sm[];
    float* sFt = sm;            // [64][132] feats^T (k-major)
    float* sW  = sm + 64*132;   // [64][64]
    int tid = threadIdx.x;
    if (blockIdx.x == 0) {
        if (tid < 64) g_sum[tid] = 0.f;
        else if (tid < 128) g_sumsq[tid-64] = 0.f;
    }
    int R0 = blockIdx.x * 128;
    // load feats tile transposed
    for (int i = tid; i < 128*16; i += 256) {
        int r = i >> 4, c4 = (i & 15) << 2;
        float4 v = *(const float4*)(feats + (size_t)(R0 + r)*64 + c4);
        sFt[(c4+0)*132 + r] = v.x;
        sFt[(c4+1)*132 + r] = v.y;
        sFt[(c4+2)*132 + r] = v.z;
        sFt[(c4+3)*132 + r] = v.w;
    }
    int tm = tid >> 5, tn = tid & 31, c0 = tn * 2;
    const float* Ws[3] = {wq, wk, wv};
    float* Os[3] = {g_q, g_kf, g_vf};
    for (int mat = 0; mat < 3; mat++) {
        __syncthreads();   // sFt ready (mat 0) / previous GEMM done reading sW
        for (int i = tid; i < 1024; i += 256)
            *(float4*)(sW + i*4) = *(const float4*)(Ws[mat] + i*4);
        __syncthreads();
        float a0[16], a1[16];
        #pragma unroll
        for (int s = 0; s < 16; s++) { a0[s] = 0.f; a1[s] = 0.f; }
        for (int kk = 0; kk < 64; kk++) {
            float2 w = *(const float2*)(sW + kk*64 + c0);
            const float4* ap = (const float4*)(sFt + kk*132 + (tm<<4));
            #pragma unroll
            for (int q4 = 0; q4 < 4; q4++) {
                float4 a = ap[q4];
                a0[q4*4+0] += a.x*w.x;  a1[q4*4+0] += a.x*w.y;
                a0[q4*4+1] += a.y*w.x;  a1[q4*4+1] += a.y*w.y;
                a0[q4*4+2] += a.z*w.x;  a1[q4*4+2] += a.z*w.y;
                a0[q4*4+3] += a.w*w.x;  a1[q4*4+3] += a.w*w.y;
            }
        }
        float* O = Os[mat];
        #pragma unroll
        for (int s = 0; s < 16; s++) {
            float2 v = make_float2(a0[s], a1[s]);
            *(float2*)(O + (size_t)(R0 + (tm<<4) + s)*64 + c0) = v;
        }
    }
}

// ---------------- K2: KNN (top-16 smallest squared distances per point) --------
// grid 64 x 256 thr; 1 thread = 1 query; candidate tiles of 512 in shared.
__global__ void __launch_bounds__(256) knn_kernel(const float* __restrict__ xyz)
{
    __shared__ float sx[512], sy[512], sz[512], ssq[512];
    int tid = threadIdx.x;
    int b = blockIdx.x >> 5;
    int n = ((blockIdx.x & 31) << 8) + tid;
    const float* base = xyz + (size_t)b * NN * 3;
    float qx = base[n*3], qy = base[n*3+1], qz = base[n*3+2];
    float qsq = fmaf(qz, qz, fmaf(qy, qy, qx*qx));

    float d16[KNBR]; int i16[KNBR];
    #pragma unroll
    for (int s = 0; s < KNBR; s++) { d16[s] = 3.4e38f; i16[s] = -1; }
    float worst = 3.4e38f;

    for (int t0 = 0; t0 < NN; t0 += 512) {
        __syncthreads();
        for (int i = tid; i < 512; i += 256) {
            int j = t0 + i;
            float x = base[j*3], y = base[j*3+1], z = base[j*3+2];
            sx[i] = x; sy[i] = y; sz[i] = z;
            ssq[i] = fmaf(z, z, fmaf(y, y, x*x));
        }
        __syncthreads();
        #pragma unroll 4
        for (int i = 0; i < 512; i++) {
            float dot = fmaf(qz, sz[i], fmaf(qy, sy[i], qx*sx[i]));
            float d = qsq + ssq[i] - 2.0f * dot;   // same expansion form as reference
            if (d < worst) {
                bool done = false;
                #pragma unroll
                for (int s = 0; s < KNBR; s++) {
                    if (!done && d16[s] == worst) { d16[s] = d; i16[s] = t0 + i; done = true; }
                }
                worst = d16[0];
                #pragma unroll
                for (int s = 1; s < KNBR; s++) worst = fmaxf(worst, d16[s]);
            }
        }
    }
    size_t ob = ((size_t)(b * NN + n)) * KNBR;
    #pragma unroll
    for (int s = 0; s < KNBR; s++) g_knn[ob + s] = i16[s];
}

// ---------------- K3: mega fused kernel -----------------------------------------
// 2048 blocks x 256 thr; block = 8 points (128 (n,k) rows).
// Stages (all in shared, k-major [64][132] with pad):
//   H1 = relu(dxyz@W1d+b1d)  -> sA
//   pos = H1@W2d+b2d (regs)  -> x = q-kf+pos -> sA ; val = vf+pos (regs)
//   g1 = relu(x@W1g+b1g)     -> sA
//   logits = g1@W2g+b2g (regs) -> per-thread softmax over K -> res -> g_res + BN partials
#define FUSED_SMEM ((64*132 + 3*64*64 + 192 + 256 + 128)*4)
__global__ void __launch_bounds__(256, 2) fused_kernel(
    const float* __restrict__ xyz, const float* __restrict__ feats,
    const float* __restrict__ w1d, const float* __restrict__ b1d,
    const float* __restrict__ w2d, const float* __restrict__ b2d,
    const float* __restrict__ w1g, const float* __restrict__ b1g,
    const float* __restrict__ w2g, const float* __restrict__ b2g)
{
    extern __shared__ float sm[];
    float* sA   = sm;                 // [64][132]
    float* sW2d = sA   + 64*132;      // [64][64]
    float* sW1g = sW2d + 4096;
    float* sW2g = sW1g + 4096;
    float* sW1d = sW2g + 4096;        // [3][64]
    float* sB   = sW1d + 192;         // b1d|b2d|b1g|b2g
    int*   sIdx = (int*)(sB + 256);   // [128]
    int tid = threadIdx.x;

    for (int i = tid; i < 1024; i += 256) {
        *(float4*)(sW2d + i*4) = *(const float4*)(w2d + i*4);
        *(float4*)(sW1g + i*4) = *(const float4*)(w1g + i*4);
        *(float4*)(sW2g + i*4) = *(const float4*)(w2g + i*4);
    }
    if (tid < 192) sW1d[tid] = w1d[tid];
    if (tid < 64) { sB[tid] = b1d[tid]; sB[64+tid] = b2d[tid]; sB[128+tid] = b1g[tid]; sB[192+tid] = b2g[tid]; }

    int R0 = blockIdx.x * 128;
    int P0 = blockIdx.x * 8;
    int b  = P0 >> 13;                 // all 8 points in same batch (8192 % 8 == 0)
    __syncthreads();                   // weights + biases ready

    // ---- stage H1 into sA (transposed) ----
    {
        int m   = tid >> 1;
        int row = R0 + m;
        int pn  = row >> 4;
        int nl  = pn & (NN - 1);
        int j   = g_knn[row];
        if ((tid & 1) == 0) sIdx[m] = j;
        const float* xb = xyz + (size_t)b * NN * 3;
        float dx = xb[nl*3+0] - xb[j*3+0];
        float dy = xb[nl*3+1] - xb[j*3+1];
        float dz = xb[nl*3+2] - xb[j*3+2];
        int cb = (tid & 1) * 32;
        #pragma unroll 8
        for (int c = 0; c < 32; c++) {
            int cc = cb + c;
            float h = fmaf(dz, sW1d[128+cc], fmaf(dy, sW1d[64+cc], fmaf(dx, sW1d[cc], sB[cc])));
            sA[cc*132 + m] = fmaxf(h, 0.f);
        }
    }
    __syncthreads();

    int tm = tid >> 5, tn = tid & 31, c0 = tn * 2;
    int mbase = tm << 4;
    int pn0 = P0 + tm;

    // ---- GEMM1: pos = H1 @ W2d + b2d ----
    float v0[KNBR], v1[KNBR];
    {
        float bb0 = sB[64+c0], bb1 = sB[64+c0+1];
        #pragma unroll
        for (int s = 0; s < KNBR; s++) { v0[s] = bb0; v1[s] = bb1; }
        for (int kk = 0; kk < 64; kk++) {
            float2 w = *(const float2*)(sW2d + kk*64 + c0);
            const float4* ap = (const float4*)(sA + kk*132 + mbase);
            #pragma unroll
            for (int q4 = 0; q4 < 4; q4++) {
                float4 a = ap[q4];
                v0[q4*4+0] += a.x*w.x;  v1[q4*4+0] += a.x*w.y;
                v0[q4*4+1] += a.y*w.x;  v1[q4*4+1] += a.y*w.y;
                v0[q4*4+2] += a.z*w.x;  v1[q4*4+2] += a.z*w.y;
                v0[q4*4+3] += a.w*w.x;  v1[q4*4+3] += a.w*w.y;
            }
        }
    }
    __syncthreads();   // done reading H1 from sA

    // ---- epilogue: x = q - kf + pos -> sA ; val = vf + pos (in v0/v1) ----
    {
        float2 qv = *(const float2*)(g_q + (size_t)pn0*64 + c0);
        #pragma unroll
        for (int s = 0; s < KNBR; s++) {
            int j = sIdx[mbase + s];
            size_t gp = ((size_t)(b*NN + j))*64 + c0;
            float2 kf = *(const float2*)(g_kf + gp);
            float2 vf = *(const float2*)(g_vf + gp);
            float x0 = qv.x - kf.x + v0[s];
            float x1 = qv.y - kf.y + v1[s];
            v0[s] += vf.x;     // now val
            v1[s] += vf.y;
            sA[c0*132 + mbase + s]     = x0;
            sA[(c0+1)*132 + mbase + s] = x1;
        }
    }
    __syncthreads();

    // ---- GEMM2: g1 = relu(x @ W1g + b1g) ----
    float t0a[KNBR], t1a[KNBR];
    {
        float bb0 = sB[128+c0], bb1 = sB[128+c0+1];
        #pragma unroll
        for (int s = 0; s < KNBR; s++) { t0a[s] = bb0; t1a[s] = bb1; }
        for (int kk = 0; kk < 64; kk++) {
            float2 w = *(const float2*)(sW1g + kk*64 + c0);
            const float4* ap = (const float4*)(sA + kk*132 + mbase);
            #pragma unroll
            for (int q4 = 0; q4 < 4; q4++) {
                float4 a = ap[q4];
                t0a[q4*4+0] += a.x*w.x;  t1a[q4*4+0] += a.x*w.y;
                t0a[q4*4+1] += a.y*w.x;  t1a[q4*4+1] += a.y*w.y;
                t0a[q4*4+2] += a.z*w.x;  t1a[q4*4+2] += a.z*w.y;
                t0a[q4*4+3] += a.w*w.x;  t1a[q4*4+3] += a.w*w.y;
            }
        }
    }
    __syncthreads();   // done reading x
    #pragma unroll
    for (int s = 0; s < KNBR; s++) {
        sA[c0*132 + mbase + s]     = fmaxf(t0a[s], 0.f);
        sA[(c0+1)*132 + mbase + s] = fmaxf(t1a[s], 0.f);
    }
    __syncthreads();

    // ---- GEMM3: logits = g1 @ W2g + b2g ----
    {
        float bb0 = sB[192+c0], bb1 = sB[192+c0+1];
        #pragma unroll
        for (int s = 0; s < KNBR; s++) { t0a[s] = bb0; t1a[s] = bb1; }
        for (int kk = 0; kk < 64; kk++) {
            float2 w = *(const float2*)(sW2g + kk*64 + c0);
            const float4* ap = (const float4*)(sA + kk*132 + mbase);
            #pragma unroll
            for (int q4 = 0; q4 < 4; q4++) {
                float4 a = ap[q4];
                t0a[q4*4+0] += a.x*w.x;  t1a[q4*4+0] += a.x*w.y;
                t0a[q4*4+1] += a.y*w.x;  t1a[q4*4+1] += a.y*w.y;
                t0a[q4*4+2] += a.z*w.x;  t1a[q4*4+2] += a.z*w.y;
                t0a[q4*4+3] += a.w*w.x;  t1a[q4*4+3] += a.w*w.y;
            }
        }
    }

    // ---- softmax over K (thread-local) + weighted sum + residual ----
    float m0 = t0a[0], m1 = t1a[0];
    #pragma unroll
    for (int s = 1; s < KNBR; s++) { m0 = fmaxf(m0, t0a[s]); m1 = fmaxf(m1, t1a[s]); }
    float s0 = 0.f, s1 = 0.f;
    #pragma unroll
    for (int s = 0; s < KNBR; s++) {
        t0a[s] = __expf(t0a[s] - m0);  s0 += t0a[s];
        t1a[s] = __expf(t1a[s] - m1);  s1 += t1a[s];
    }
    float r0 = 0.f, r1 = 0.f;
    #pragma unroll
    for (int s = 0; s < KNBR; s++) { r0 = fmaf(t0a[s], v0[s], r0); r1 = fmaf(t1a[s], v1[s], r1); }
    float2 fv = *(const float2*)(feats + (size_t)pn0*64 + c0);
    r0 = r0 / s0 + fv.x;
    r1 = r1 / s1 + fv.y;
    *(float2*)(g_res + (size_t)pn0*64 + c0) = make_float2(r0, r1);

    // ---- BN partial sums ----
    __syncthreads();   // sA free
    if (tid < 128) sA[tid] = 0.f;
    __syncthreads();
    atomicAdd(&sA[c0],      r0);
    atomicAdd(&sA[c0+1],    r1);
    atomicAdd(&sA[64+c0],   r0*r0);
    atomicAdd(&sA[64+c0+1], r1*r1);
    __syncthreads();
    if (tid < 64) {
        atomicAdd(&g_sum[tid],   sA[tid]);
        atomicAdd(&g_sumsq[tid], sA[64+tid]);
    }
}

// ---------------- K4: BatchNorm apply ----------------
__global__ void __launch_bounds__(256) bn_kernel(
    const float* __restrict__ bn_gamma, const float* __restrict__ bn_beta,
    float* __restrict__ out)
{
    int idx = blockIdx.x * 256 + threadIdx.x;
    int c = idx & 63;
    float inv = 1.0f / (float)NPTS;
    float mean = g_sum[c] * inv;
    float var  = g_sumsq[c] * inv - mean * mean;
    out[idx] = (g_res[idx] - mean) * rsqrtf(var + 1e-5f) * bn_gamma[c] + bn_beta[c];
}

// ---------------- launch ----------------
extern "C" void kernel_launch(void* const* d_in, const int* in_sizes, int n_in,
                              void* d_out, int out_size)
{
    const float* xyz   = (const float*)d_in[0];
    const float* feats = (const float*)d_in[1];
    const float* wq    = (const float*)d_in[2];
    const float* wk    = (const float*)d_in[3];
    const float* wv    = (const float*)d_in[4];
    const float* dw1   = (const float*)d_in[5];
    const float* db1   = (const float*)d_in[6];
    const float* dw2   = (const float*)d_in[7];
    const float* db2   = (const float*)d_in[8];
    const float* gw1   = (const float*)d_in[9];
    const float* gb1   = (const float*)d_in[10];
    const float* gw2   = (const float*)d_in[11];
    const float* gb2   = (const float*)d_in[12];
    const float* bng   = (const float*)d_in[13];
    const float* bnb   = (const float*)d_in[14];
    float* out = (float*)d_out;

    cudaFuncSetAttribute(proj_kernel,  cudaFuncAttributeMaxDynamicSharedMemorySize, PROJ_SMEM);
    cudaFuncSetAttribute(fused_kernel, cudaFuncAttributeMaxDynamicSharedMemorySize, FUSED_SMEM);

    proj_kernel <<<128, 256, PROJ_SMEM>>>(feats, wq, wk, wv);
    knn_kernel  <<<64, 256>>>(xyz);
    fused_kernel<<<2048, 256, FUSED_SMEM>>>(xyz, feats, dw1, db1, dw2, db2, gw1, gb1, gw2, gb2);
    bn_kernel   <<<4096, 256>>>(bng, bnb, out);
}

// round 2
// speedup vs baseline: 1.0339x; 1.0339x over previous
#include <cuda_runtime.h>
#include <math.h>

#define BB 2
#define NN 8192
#define DD 64
#define KNBR 16
#define NPTS (BB*NN)          // 16384
#define ROWS (NPTS*KNBR)      // 262144
#define KP 4                  // knn partitions per query
#define CHUNK (NN/KP)         // 2048

// ---------------- scratch (static device arrays; no allocation) ----------------
__device__ float g_q  [NPTS*DD];
__device__ float g_kf [NPTS*DD];
__device__ float g_vf [NPTS*DD];
__device__ int   g_knn[ROWS];
__device__ float g_res[NPTS*DD];
__device__ float g_sum[DD];
__device__ float g_sumsq[DD];
__device__ float g_pd[NPTS*KP*KNBR];
__device__ int   g_pi[NPTS*KP*KNBR];

// ---------------- packed f32x2 helpers ----------------
__device__ __forceinline__ void fma2(unsigned long long &d, unsigned long long a, unsigned long long b) {
    asm("fma.rn.f32x2 %0, %1, %2, %0;" : "+l"(d) : "l"(a), "l"(b));
}
__device__ __forceinline__ unsigned long long pk2(float lo, float hi) {
    unsigned long long r; asm("mov.b64 %0, {%1,%2};" : "=l"(r) : "f"(lo), "f"(hi)); return r;
}
__device__ __forceinline__ float2 up2(unsigned long long v) {
    float2 r; asm("mov.b64 {%0,%1}, %2;" : "=f"(r.x), "=f"(r.y) : "l"(v)); return r;
}

// 128x64 GEMM slice: thread computes 16 rows (mbase..mbase+15) x 2 cols (2*tn, 2*tn+1).
// sA: k-major [64][132]. sWd: duplicated weights [64][128] where [kk][2c]=[kk][2c+1]=W[kk][c].
// Accumulators are f32x2 pairs along rows: a0[p]=(out[2p],out[2p+1]) col 2tn; a1 col 2tn+1.
__device__ __forceinline__ void gemm_f32x2(const float* __restrict__ sA, const float* __restrict__ sWd,
                                           int mbase, int tn,
                                           unsigned long long* a0, unsigned long long* a1)
{
    #pragma unroll 4
    for (int kk = 0; kk < 64; kk++) {
        const ulonglong2* ap = (const ulonglong2*)(sA + kk*132 + mbase);     // broadcast LDS.128
        ulonglong2 w = *(const ulonglong2*)(sWd + kk*128 + 4*tn);            // (wc0,wc0,wc1,wc1)
        ulonglong2 A0 = ap[0], A1 = ap[1];
        fma2(a0[0], A0.x, w.x); fma2(a1[0], A0.x, w.y);
        fma2(a0[1], A0.y, w.x); fma2(a1[1], A0.y, w.y);
        fma2(a0[2], A1.x, w.x); fma2(a1[2], A1.x, w.y);
        fma2(a0[3], A1.y, w.x); fma2(a1[3], A1.y, w.y);
        ulonglong2 A2 = ap[2], A3 = ap[3];
        fma2(a0[4], A2.x, w.x); fma2(a1[4], A2.x, w.y);
        fma2(a0[5], A2.y, w.x); fma2(a1[5], A2.y, w.y);
        fma2(a0[6], A3.x, w.x); fma2(a1[6], A3.x, w.y);
        fma2(a0[7], A3.y, w.x); fma2(a1[7], A3.y, w.y);
    }
}

// ---------------- K1: projections q,k,v = feats @ W ----------------
#define PROJ_SMEM ((64*132 + 64*128)*4)
__global__ void __launch_bounds__(256) proj_kernel(
    const float* __restrict__ feats,
    const float* __restrict__ wq, const float* __restrict__ wk, const float* __restrict__ wv)
{
    extern __shared__ float sm[];
    float* sFt = sm;            // [64][132] feats^T (k-major)
    float* sWd = sm + 64*132;   // [64][128] duplicated
    int tid = threadIdx.x;
    if (blockIdx.x == 0) {
        if (tid < 64) g_sum[tid] = 0.f;
        else if (tid < 128) g_sumsq[tid-64] = 0.f;
    }
    int R0 = blockIdx.x * 128;
    for (int i = tid; i < 128*16; i += 256) {
        int r = i >> 4, c4 = (i & 15) << 2;
        float4 v = *(const float4*)(feats + (size_t)(R0 + r)*64 + c4);
        sFt[(c4+0)*132 + r] = v.x;
        sFt[(c4+1)*132 + r] = v.y;
        sFt[(c4+2)*132 + r] = v.z;
        sFt[(c4+3)*132 + r] = v.w;
    }
    int tm = tid >> 5, tn = tid & 31, c0 = tn * 2;
    int mbase = tm << 4;
    const float* Ws[3] = {wq, wk, wv};
    float* Os[3] = {g_q, g_kf, g_vf};
    for (int mat = 0; mat < 3; mat++) {
        __syncthreads();
        const float* W = Ws[mat];
        for (int i = tid; i < 4096; i += 256) {
            int kk = i >> 6, c = i & 63;
            float w = W[i];
            *(float2*)(sWd + kk*128 + 2*c) = make_float2(w, w);
        }
        __syncthreads();
        unsigned long long a0[8], a1[8];
        #pragma unroll
        for (int p = 0; p < 8; p++) { a0[p] = 0ull; a1[p] = 0ull; }
        gemm_f32x2(sFt, sWd, mbase, tn, a0, a1);
        float* O = Os[mat];
        #pragma unroll
        for (int p = 0; p < 8; p++) {
            float2 r0 = up2(a0[p]);   // col c0, rows 2p,2p+1
            float2 r1 = up2(a1[p]);   // col c0+1
            *(float2*)(O + (size_t)(R0 + mbase + 2*p)*64 + c0)   = make_float2(r0.x, r1.x);
            *(float2*)(O + (size_t)(R0 + mbase + 2*p+1)*64 + c0) = make_float2(r0.y, r1.y);
        }
    }
}

// ---------------- K2a: partial KNN (each thread: 1 query x 1/KP of candidates) ----
// grid 256 = B(2) x KP(4) x 32 groups; block 256 threads = 256 queries.
__global__ void __launch_bounds__(256) knn_part_kernel(const float* __restrict__ xyz)
{
    __shared__ float4 sc[512];
    int tid = threadIdx.x;
    int b = blockIdx.x >> 7;
    int p = (blockIdx.x >> 5) & 3;
    int n = ((blockIdx.x & 31) << 8) + tid;
    const float* base = xyz + (size_t)b * NN * 3;
    float qx = base[n*3], qy = base[n*3+1], qz = base[n*3+2];
    float qsq = fmaf(qz, qz, fmaf(qy, qy, qx*qx));

    float d16[KNBR]; int i16[KNBR];
    #pragma unroll
    for (int s = 0; s < KNBR; s++) { d16[s] = 3.4e38f; i16[s] = -1; }
    float worst = 3.4e38f;

    for (int t0 = p*CHUNK; t0 < (p+1)*CHUNK; t0 += 512) {
        __syncthreads();
        for (int i = tid; i < 512; i += 256) {
            int j = t0 + i;
            float x = base[j*3], y = base[j*3+1], z = base[j*3+2];
            sc[i] = make_float4(x, y, z, fmaf(z, z, fmaf(y, y, x*x)));
        }
        __syncthreads();
        #pragma unroll 4
        for (int i = 0; i < 512; i++) {
            float4 c = sc[i];
            float dot = fmaf(qz, c.z, fmaf(qy, c.y, qx*c.x));
            float d = qsq + c.w - 2.0f * dot;   // same expansion form as reference
            if (d < worst) {
                bool done = false;
                #pragma unroll
                for (int s = 0; s < KNBR; s++) {
                    if (!done && d16[s] == worst) { d16[s] = d; i16[s] = t0 + i; done = true; }
                }
                worst = d16[0];
                #pragma unroll
                for (int s = 1; s < KNBR; s++) worst = fmaxf(worst, d16[s]);
            }
        }
    }
    size_t ob = (((size_t)(b * NN + n))*KP + p) * KNBR;
    #pragma unroll
    for (int s = 0; s < KNBR; s++) { g_pd[ob + s] = d16[s]; g_pi[ob + s] = i16[s]; }
}

// ---------------- K2b: merge KP x 16 partials -> top 16 ----------------
__global__ void __launch_bounds__(256) knn_merge_kernel()
{
    int q = blockIdx.x * 256 + threadIdx.x;   // 64 blocks
    const float* pd = g_pd + (size_t)q * (KP*KNBR);
    const int*   pi = g_pi + (size_t)q * (KP*KNBR);
    float d16[KNBR]; int i16[KNBR];
    #pragma unroll
    for (int s = 0; s < KNBR; s++) { d16[s] = pd[s]; i16[s] = pi[s]; }
    float worst = d16[0];
    #pragma unroll
    for (int s = 1; s < KNBR; s++) worst = fmaxf(worst, d16[s]);
    for (int i = KNBR; i < KP*KNBR; i++) {
        float d = pd[i];
        if (d < worst) {
            int ii = pi[i];
            bool done = false;
            #pragma unroll
            for (int s = 0; s < KNBR; s++) {
                if (!done && d16[s] == worst) { d16[s] = d; i16[s] = ii; done = true; }
            }
            worst = d16[0];
            #pragma unroll
            for (int s = 1; s < KNBR; s++) worst = fmaxf(worst, d16[s]);
        }
    }
    #pragma unroll
    for (int s = 0; s < KNBR; s++) g_knn[(size_t)q*KNBR + s] = i16[s];
}

// ---------------- K3: mega fused kernel ----------------
// 2048 blocks x 256 thr; block = 8 points (128 (n,k) rows). f32x2 GEMMs.
#define FUSED_SMEM ((64*132 + 3*64*128 + 192 + 256 + 128)*4)
__global__ void __launch_bounds__(256) fused_kernel(
    const float* __restrict__ xyz, const float* __restrict__ feats,
    const float* __restrict__ w1d, const float* __restrict__ b1d,
    const float* __restrict__ w2d, const float* __restrict__ b2d,
    const float* __restrict__ w1g, const float* __restrict__ b1g,
    const float* __restrict__ w2g, const float* __restrict__ b2g)
{
    extern __shared__ float sm[];
    float* sA    = sm;                  // [64][132]
    float* sWd2d = sA    + 64*132;      // [64][128] dup
    float* sWd1g = sWd2d + 64*128;
    float* sWd2g = sWd1g + 64*128;
    float* sW1d  = sWd2g + 64*128;      // [3][64]
    float* sB    = sW1d + 192;          // b1d|b2d|b1g|b2g
    int*   sIdx  = (int*)(sB + 256);    // [128]
    int tid = threadIdx.x;

    for (int i = tid; i < 4096; i += 256) {
        int kk = i >> 6, c = i & 63;
        float wa = w2d[i], wb = w1g[i], wc = w2g[i];
        *(float2*)(sWd2d + kk*128 + 2*c) = make_float2(wa, wa);
        *(float2*)(sWd1g + kk*128 + 2*c) = make_float2(wb, wb);
        *(float2*)(sWd2g + kk*128 + 2*c) = make_float2(wc, wc);
    }
    if (tid < 192) sW1d[tid] = w1d[tid];
    if (tid < 64) { sB[tid] = b1d[tid]; sB[64+tid] = b2d[tid]; sB[128+tid] = b1g[tid]; sB[192+tid] = b2g[tid]; }

    int R0 = blockIdx.x * 128;
    int P0 = blockIdx.x * 8;
    int b  = P0 >> 13;
    __syncthreads();

    // ---- stage H1 = relu(dxyz @ W1d + b1d) into sA (k-major) ----
    {
        int m   = tid >> 1;
        int row = R0 + m;
        int pn  = row >> 4;
        int nl  = pn & (NN - 1);
        int j   = g_knn[row];
        if ((tid & 1) == 0) sIdx[m] = j;
        const float* xb = xyz + (size_t)b * NN * 3;
        float dx = xb[nl*3+0] - xb[j*3+0];
        float dy = xb[nl*3+1] - xb[j*3+1];
        float dz = xb[nl*3+2] - xb[j*3+2];
        int cb = (tid & 1) * 32;
        #pragma unroll 8
        for (int c = 0; c < 32; c++) {
            int cc = cb + c;
            float h = fmaf(dz, sW1d[128+cc], fmaf(dy, sW1d[64+cc], fmaf(dx, sW1d[cc], sB[cc])));
            sA[cc*132 + m] = fmaxf(h, 0.f);
        }
    }
    __syncthreads();

    int tm = tid >> 5, tn = tid & 31, c0 = tn * 2;
    int mbase = tm << 4;
    int pn0 = P0 + tm;

    // ---- GEMM1: pos = H1 @ W2d + b2d ----
    unsigned long long a0[8], a1[8];
    {
        unsigned long long bb0 = pk2(sB[64+c0],   sB[64+c0]);
        unsigned long long bb1 = pk2(sB[64+c0+1], sB[64+c0+1]);
        #pragma unroll
        for (int p = 0; p < 8; p++) { a0[p] = bb0; a1[p] = bb1; }
        gemm_f32x2(sA, sWd2d, mbase, tn, a0, a1);
    }
    __syncthreads();   // done reading H1

    // ---- epilogue: x = q - kf + pos -> sA ; val = vf + pos -> v0/v1 ----
    float v0[KNBR], v1[KNBR];
    {
        float2 qv = *(const float2*)(g_q + (size_t)pn0*64 + c0);
        #pragma unroll
        for (int p = 0; p < 8; p++) {
            float2 ps0 = up2(a0[p]);  // pos col c0, s=2p / 2p+1
            float2 ps1 = up2(a1[p]);  // pos col c0+1
            int j0 = sIdx[mbase + 2*p];
            int j1 = sIdx[mbase + 2*p + 1];
            size_t gp0 = ((size_t)(b*NN + j0))*64 + c0;
            size_t gp1 = ((size_t)(b*NN + j1))*64 + c0;
            float2 kf0 = *(const float2*)(g_kf + gp0);
            float2 kf1 = *(const float2*)(g_kf + gp1);
            float2 vf0 = *(const float2*)(g_vf + gp0);
            float2 vf1 = *(const float2*)(g_vf + gp1);
            v0[2*p]   = vf0.x + ps0.x;  v1[2*p]   = vf0.y + ps1.x;
            v0[2*p+1] = vf1.x + ps0.y;  v1[2*p+1] = vf1.y + ps1.y;
            *(float2*)(sA + c0*132     + mbase + 2*p) = make_float2(qv.x - kf0.x + ps0.x, qv.x - kf1.x + ps0.y);
            *(float2*)(sA + (c0+1)*132 + mbase + 2*p) = make_float2(qv.y - kf0.y + ps1.x, qv.y - kf1.y + ps1.y);
        }
    }
    __syncthreads();

    // ---- GEMM2: g1 = relu(x @ W1g + b1g) ----
    {
        unsigned long long bb0 = pk2(sB[128+c0],   sB[128+c0]);
        unsigned long long bb1 = pk2(sB[128+c0+1], sB[128+c0+1]);
        #pragma unroll
        for (int p = 0; p < 8; p++) { a0[p] = bb0; a1[p] = bb1; }
        gemm_f32x2(sA, sWd1g, mbase, tn, a0, a1);
    }
    __syncthreads();   // done reading x
    #pragma unroll
    for (int p = 0; p < 8; p++) {
        float2 r0 = up2(a0[p]), r1 = up2(a1[p]);
        *(float2*)(sA + c0*132     + mbase + 2*p) = make_float2(fmaxf(r0.x,0.f), fmaxf(r0.y,0.f));
        *(float2*)(sA + (c0+1)*132 + mbase + 2*p) = make_float2(fmaxf(r1.x,0.f), fmaxf(r1.y,0.f));
    }
    __syncthreads();

    // ---- GEMM3: logits = g1 @ W2g + b2g ----
    {
        unsigned long long bb0 = pk2(sB[192+c0],   sB[192+c0]);
        unsigned long long bb1 = pk2(sB[192+c0+1], sB[192+c0+1]);
        #pragma unroll
        for (int p = 0; p < 8; p++) { a0[p] = bb0; a1[p] = bb1; }
        gemm_f32x2(sA, sWd2g, mbase, tn, a0, a1);
    }

    // ---- softmax over K (thread-local) + weighted sum + residual ----
    float t0a[KNBR], t1a[KNBR];
    #pragma unroll
    for (int p = 0; p < 8; p++) {
        float2 r0 = up2(a0[p]), r1 = up2(a1[p]);
        t0a[2*p] = r0.x; t0a[2*p+1] = r0.y;
        t1a[2*p] = r1.x; t1a[2*p+1] = r1.y;
    }
    float m0 = t0a[0], m1 = t1a[0];
    #pragma unroll
    for (int s = 1; s < KNBR; s++) { m0 = fmaxf(m0, t0a[s]); m1 = fmaxf(m1, t1a[s]); }
    float s0 = 0.f, s1 = 0.f;
    #pragma unroll
    for (int s = 0; s < KNBR; s++) {
        t0a[s] = __expf(t0a[s] - m0);  s0 += t0a[s];
        t1a[s] = __expf(t1a[s] - m1);  s1 += t1a[s];
    }
    float r0 = 0.f, r1 = 0.f;
    #pragma unroll
    for (int s = 0; s < KNBR; s++) { r0 = fmaf(t0a[s], v0[s], r0); r1 = fmaf(t1a[s], v1[s], r1); }
    float2 fv = *(const float2*)(feats + (size_t)pn0*64 + c0);
    r0 = r0 / s0 + fv.x;
    r1 = r1 / s1 + fv.y;
    *(float2*)(g_res + (size_t)pn0*64 + c0) = make_float2(r0, r1);

    // ---- BN partial sums ----
    __syncthreads();
    if (tid < 128) sA[tid] = 0.f;
    __syncthreads();
    atomicAdd(&sA[c0],      r0);
    atomicAdd(&sA[c0+1],    r1);
    atomicAdd(&sA[64+c0],   r0*r0);
    atomicAdd(&sA[64+c0+1], r1*r1);
    __syncthreads();
    if (tid < 64) {
        atomicAdd(&g_sum[tid],   sA[tid]);
        atomicAdd(&g_sumsq[tid], sA[64+tid]);
    }
}

// ---------------- K4: BatchNorm apply ----------------
__global__ void __launch_bounds__(256) bn_kernel(
    const float* __restrict__ bn_gamma, const float* __restrict__ bn_beta,
    float* __restrict__ out)
{
    int idx = blockIdx.x * 256 + threadIdx.x;
    int c = idx & 63;
    float inv = 1.0f / (float)NPTS;
    float mean = g_sum[c] * inv;
    float var  = g_sumsq[c] * inv - mean * mean;
    out[idx] = (g_res[idx] - mean) * rsqrtf(var + 1e-5f) * bn_gamma[c] + bn_beta[c];
}

// ---------------- launch ----------------
extern "C" void kernel_launch(void* const* d_in, const int* in_sizes, int n_in,
                              void* d_out, int out_size)
{
    const float* xyz   = (const float*)d_in[0];
    const float* feats = (const float*)d_in[1];
    const float* wq    = (const float*)d_in[2];
    const float* wk    = (const float*)d_in[3];
    const float* wv    = (const float*)d_in[4];
    const float* dw1   = (const float*)d_in[5];
    const float* db1   = (const float*)d_in[6];
    const float* dw2   = (const float*)d_in[7];
    const float* db2   = (const float*)d_in[8];
    const float* gw1   = (const float*)d_in[9];
    const float* gb1   = (const float*)d_in[10];
    const float* gw2   = (const float*)d_in[11];
    const float* gb2   = (const float*)d_in[12];
    const float* bng   = (const float*)d_in[13];
    const float* bnb   = (const float*)d_in[14];
    float* out = (float*)d_out;

    cudaFuncSetAttribute(proj_kernel,  cudaFuncAttributeMaxDynamicSharedMemorySize, PROJ_SMEM);
    cudaFuncSetAttribute(fused_kernel, cudaFuncAttributeMaxDynamicSharedMemorySize, FUSED_SMEM);

    knn_part_kernel <<<256, 256>>>(xyz);
    proj_kernel     <<<128, 256, PROJ_SMEM>>>(feats, wq, wk, wv);
    knn_merge_kernel<<<64, 256>>>();
    fused_kernel    <<<2048, 256, FUSED_SMEM>>>(xyz, feats, dw1, db1, dw2, db2, gw1, gb1, gw2, gb2);
    bn_kernel       <<<4096, 256>>>(bng, bnb, out);
}